// round 9
// baseline (speedup 1.0000x reference)
#include <cuda_runtime.h>

#define NPTS 4096
#define TPB 256
#define ITILES 8             // 8 i-tiles x 512 i each (2 queries/thread)
#define JCHUNKS 111          // 8*111 = 888 blocks = one wave @ 6 CTAs/SM on 148 SMs
#define CHUNK 37             // 111*37 = 4107 >= 4096, padded, branch-free
#define NBLOCKS (ITILES * JCHUNKS)
#define FING 128             // finalize: 128 blocks x 32 i's (lane = i)

__device__ float4 g_pden[JCHUNKS * NPTS];
__device__ float4 g_pnum[JCHUNKS * NPTS];
__device__ unsigned g_ctr  = 0;
__device__ unsigned g_done = 0;

__device__ __forceinline__ float ex2f(float x) {
    float y;
    asm("ex2.approx.ftz.f32 %0, %1;" : "=f"(y) : "f"(x));
    return y;
}
// fixed fma order so hot loop, prep and finalize produce identical bits
__device__ __forceinline__ float dotw(float4 r, const float* __restrict__ W, int c) {
    float d = r.x * __ldg(W + c*4 + 0);
    d = fmaf(r.y, __ldg(W + c*4 + 1), d);
    d = fmaf(r.z, __ldg(W + c*4 + 2), d);
    d = fmaf(r.w, __ldg(W + c*4 + 3), d);
    return d;
}

// k'_{j,i,c} = 2^{a_j*(2 b_i) - a_j^2}; the per-i factor 2^{-b_i^2} cancels in the ratio.
// s = sqrt(0.5*log2 e)/h. Hot cost per pair-channel: 1 FFMA + 1 EX2 + 1 FADD + 1 FFMA.
__global__ void __launch_bounds__(TPB, 6) fused_kernel(
    const float* __restrict__ x,   // [4096,4]
    const float* __restrict__ tx,  // [4096,4]
    const float* __restrict__ Y,   // [4096,3]
    const float* __restrict__ W,   // [3,4]
    const float* __restrict__ h,   // [1]
    float* __restrict__ out)       // [4096,3]
{
    __shared__ float4 sA[CHUNK], sQ[CHUNK], sY[CHUNK];   // sQ holds -a^2

    const int tid = threadIdx.x, bx = blockIdx.x, by = blockIdx.y;
    const float s  = sqrtf(0.5f * 1.44269504088896340736f) / __ldg(h);
    const float s2 = s + s;

    // ---- prep this block's j-chunk into smem (tid < CHUNK, one row each) ----
    if (tid < CHUNK) {
        int j = by * CHUNK + tid;
        if (j < NPTS) {
            float4 xt = __ldg(reinterpret_cast<const float4*>(tx) + j);
            float a0 = dotw(xt, W, 0) * s;
            float a1 = dotw(xt, W, 1) * s;
            float a2 = dotw(xt, W, 2) * s;
            sA[tid] = make_float4(a0, a1, a2, 0.f);
            sQ[tid] = make_float4(-(a0*a0), -(a1*a1), -(a2*a2), 0.f);
            sY[tid] = make_float4(__ldg(Y+3*j), __ldg(Y+3*j+1), __ldg(Y+3*j+2), 0.f);
        } else {
            sA[tid] = make_float4(0.f, 0.f, 0.f, 0.f);
            sQ[tid] = make_float4(-3e38f, -3e38f, -3e38f, 0.f); // ex2 -> 0
            sY[tid] = make_float4(0.f, 0.f, 0.f, 0.f);
        }
    }

    // ---- two query points per thread ----
    const int iA = bx * (2*TPB) + tid;
    const int iB = iA + TPB;
    float4 xqA = __ldg(reinterpret_cast<const float4*>(x) + iA);
    float4 xqB = __ldg(reinterpret_cast<const float4*>(x) + iB);
    const float tA0 = dotw(xqA,W,0)*s2, tA1 = dotw(xqA,W,1)*s2, tA2 = dotw(xqA,W,2)*s2;
    const float tB0 = dotw(xqB,W,0)*s2, tB1 = dotw(xqB,W,1)*s2, tB2 = dotw(xqB,W,2)*s2;
    __syncthreads();

    // ---- hot loop: each j-row feeds 6 EX2 (3 channels x 2 queries) ----
    float dA0=0.f,dA1=0.f,dA2=0.f, nA0=0.f,nA1=0.f,nA2=0.f;
    float dB0=0.f,dB1=0.f,dB2=0.f, nB0=0.f,nB1=0.f,nB2=0.f;
#pragma unroll 2
    for (int t = 0; t < CHUNK; ++t) {
        float4 a = sA[t];   // broadcast LDS.128
        float4 q = sQ[t];
        float4 y = sY[t];
        float e;
        e = ex2f(fmaf(a.x, tA0, q.x)); dA0 += e; nA0 = fmaf(e, y.x, nA0);
        e = ex2f(fmaf(a.y, tA1, q.y)); dA1 += e; nA1 = fmaf(e, y.y, nA1);
        e = ex2f(fmaf(a.z, tA2, q.z)); dA2 += e; nA2 = fmaf(e, y.z, nA2);
        e = ex2f(fmaf(a.x, tB0, q.x)); dB0 += e; nB0 = fmaf(e, y.x, nB0);
        e = ex2f(fmaf(a.y, tB1, q.y)); dB1 += e; nB1 = fmaf(e, y.y, nB1);
        e = ex2f(fmaf(a.z, tB2, q.z)); dB2 += e; nB2 = fmaf(e, y.z, nB2);
    }
    g_pden[by*NPTS + iA] = make_float4(dA0, dA1, dA2, 0.f);
    g_pnum[by*NPTS + iA] = make_float4(nA0, nA1, nA2, 0.f);
    g_pden[by*NPTS + iB] = make_float4(dB0, dB1, dB2, 0.f);
    g_pnum[by*NPTS + iB] = make_float4(nB0, nB1, nB2, 0.f);

    // ---- publish + device-wide ticket barrier (grid = exactly one wave) ----
    __threadfence();
    __syncthreads();
    if (tid == 0) {
        atomicAdd(&g_ctr, 1u);
        while (*((volatile unsigned*)&g_ctr) < NBLOCKS) __nanosleep(32);
    }
    __syncthreads();
    __threadfence();  // acquire

    // ---- finalize: first FING blocks, warp0 only, lane = i (coalesced) ----
    const int flat = by * ITILES + bx;
    if (flat < FING && tid < 32) {
        const int i = flat * 32 + tid;
        float D0=0.f,D1=0.f,D2=0.f, N0=0.f,N1=0.f,N2=0.f;
#pragma unroll 3
        for (int z = 0; z < JCHUNKS; ++z) {
            float4 pd = g_pden[z*NPTS + i];
            float4 pn = g_pnum[z*NPTS + i];
            D0 += pd.x; D1 += pd.y; D2 += pd.z;
            N0 += pn.x; N1 += pn.y; N2 += pn.z;
        }
        // self-pair (leave-one-out): bit-identical recompute of the loop term
        float4 xt = __ldg(reinterpret_cast<const float4*>(tx) + i);
        float4 xq = __ldg(reinterpret_cast<const float4*>(x) + i);
        float a0 = dotw(xt,W,0)*s,  a1 = dotw(xt,W,1)*s,  a2 = dotw(xt,W,2)*s;
        float t0 = dotw(xq,W,0)*s2, t1 = dotw(xq,W,1)*s2, t2 = dotw(xq,W,2)*s2;
        float k0 = ex2f(fmaf(a0, t0, -(a0*a0)));
        float k1 = ex2f(fmaf(a1, t1, -(a1*a1)));
        float k2 = ex2f(fmaf(a2, t2, -(a2*a2)));
        float y0 = __ldg(Y+3*i), y1 = __ldg(Y+3*i+1), y2 = __ldg(Y+3*i+2);
        out[3*i+0] = (N0 - k0*y0) / (D0 - k0);
        out[3*i+1] = (N1 - k1*y1) / (D1 - k1);
        out[3*i+2] = (N2 - k2*y2) / (D2 - k2);
    }

    // ---- last block resets counters -> stateless across graph replays ----
    __syncthreads();
    if (tid == 0) {
        unsigned v = atomicAdd(&g_done, 1u);
        if (v == NBLOCKS - 1) { g_ctr = 0; g_done = 0; __threadfence(); }
    }
}

extern "C" void kernel_launch(void* const* d_in, const int* in_sizes, int n_in,
                              void* d_out, int out_size) {
    const float* x  = (const float*)d_in[0];
    const float* tx = (const float*)d_in[1];
    const float* Y  = (const float*)d_in[2];
    const float* W  = (const float*)d_in[3];
    const float* h  = (const float*)d_in[4];
    float* out = (float*)d_out;

    fused_kernel<<<dim3(ITILES, JCHUNKS), TPB>>>(x, tx, Y, W, h, out);
}

// round 10
// speedup vs baseline: 1.6330x; 1.6330x over previous
#include <cuda_runtime.h>

#define NPTS 4096
#define TPB 256
#define ITILES 8             // 8 i-tiles x 512 i each (2 queries/thread)
#define JCHUNKS 74           // 8*74 = 592 blocks = exactly one wave @ 4 CTAs/SM (148 SMs)
#define CHUNK 56             // 74*56 = 4144 >= 4096, padded, branch-free
#define NBLOCKS (ITILES * JCHUNKS)
#define FING 128             // finalize blocks (flat id 0..127 -> distinct SMs)

__device__ float4 g_pden[JCHUNKS * NPTS];
__device__ float4 g_pnum[JCHUNKS * NPTS];
__device__ unsigned g_ctr  = 0;
__device__ unsigned g_done = 0;

__device__ __forceinline__ float ex2f(float x) {
    float y;
    asm("ex2.approx.ftz.f32 %0, %1;" : "=f"(y) : "f"(x));
    return y;
}
// fixed fma order so hot loop, prep and finalize produce identical bits
__device__ __forceinline__ float dotw(float4 r, const float* __restrict__ W, int c) {
    float d = r.x * __ldg(W + c*4 + 0);
    d = fmaf(r.y, __ldg(W + c*4 + 1), d);
    d = fmaf(r.z, __ldg(W + c*4 + 2), d);
    d = fmaf(r.w, __ldg(W + c*4 + 3), d);
    return d;
}

// k'_{j,i,c} = 2^{a_j*(2 b_i) - a_j^2}; per-i factor 2^{-b_i^2} cancels in the ratio.
// s = sqrt(0.5*log2 e)/h. Hot cost per pair-channel: 1 FFMA + 1 EX2 + 1 FADD + 1 FFMA.
__global__ void __launch_bounds__(TPB, 4) fused_kernel(
    const float* __restrict__ x,   // [4096,4]
    const float* __restrict__ tx,  // [4096,4]
    const float* __restrict__ Y,   // [4096,3]
    const float* __restrict__ W,   // [3,4]
    const float* __restrict__ h,   // [1]
    float* __restrict__ out)       // [4096,3]
{
    __shared__ float4 sA[CHUNK], sQ[CHUNK], sY[CHUNK];   // sQ holds -a^2
    __shared__ float sC[3][32][8];                       // finalize combine buffer

    const int tid = threadIdx.x, bx = blockIdx.x, by = blockIdx.y;
    const float s  = sqrtf(0.5f * 1.44269504088896340736f) / __ldg(h);
    const float s2 = s + s;

    // ---- prep this block's j-chunk into smem (tid < CHUNK, one row each) ----
    if (tid < CHUNK) {
        int j = by * CHUNK + tid;
        if (j < NPTS) {
            float4 xt = __ldg(reinterpret_cast<const float4*>(tx) + j);
            float a0 = dotw(xt, W, 0) * s;
            float a1 = dotw(xt, W, 1) * s;
            float a2 = dotw(xt, W, 2) * s;
            sA[tid] = make_float4(a0, a1, a2, 0.f);
            sQ[tid] = make_float4(-(a0*a0), -(a1*a1), -(a2*a2), 0.f);
            sY[tid] = make_float4(__ldg(Y+3*j), __ldg(Y+3*j+1), __ldg(Y+3*j+2), 0.f);
        } else {
            sA[tid] = make_float4(0.f, 0.f, 0.f, 0.f);
            sQ[tid] = make_float4(-3e38f, -3e38f, -3e38f, 0.f); // ex2 -> 0
            sY[tid] = make_float4(0.f, 0.f, 0.f, 0.f);
        }
    }

    // ---- two query points per thread ----
    const int iA = bx * (2*TPB) + tid;
    const int iB = iA + TPB;
    float4 xqA = __ldg(reinterpret_cast<const float4*>(x) + iA);
    float4 xqB = __ldg(reinterpret_cast<const float4*>(x) + iB);
    const float tA0 = dotw(xqA,W,0)*s2, tA1 = dotw(xqA,W,1)*s2, tA2 = dotw(xqA,W,2)*s2;
    const float tB0 = dotw(xqB,W,0)*s2, tB1 = dotw(xqB,W,1)*s2, tB2 = dotw(xqB,W,2)*s2;
    __syncthreads();

    // ---- hot loop: each j-row feeds 6 EX2 (3 channels x 2 queries) ----
    float dA0=0.f,dA1=0.f,dA2=0.f, nA0=0.f,nA1=0.f,nA2=0.f;
    float dB0=0.f,dB1=0.f,dB2=0.f, nB0=0.f,nB1=0.f,nB2=0.f;
#pragma unroll 4
    for (int t = 0; t < CHUNK; ++t) {
        float4 a = sA[t];   // broadcast LDS.128
        float4 q = sQ[t];
        float4 y = sY[t];
        float e;
        e = ex2f(fmaf(a.x, tA0, q.x)); dA0 += e; nA0 = fmaf(e, y.x, nA0);
        e = ex2f(fmaf(a.y, tA1, q.y)); dA1 += e; nA1 = fmaf(e, y.y, nA1);
        e = ex2f(fmaf(a.z, tA2, q.z)); dA2 += e; nA2 = fmaf(e, y.z, nA2);
        e = ex2f(fmaf(a.x, tB0, q.x)); dB0 += e; nB0 = fmaf(e, y.x, nB0);
        e = ex2f(fmaf(a.y, tB1, q.y)); dB1 += e; nB1 = fmaf(e, y.y, nB1);
        e = ex2f(fmaf(a.z, tB2, q.z)); dB2 += e; nB2 = fmaf(e, y.z, nB2);
    }
    g_pden[by*NPTS + iA] = make_float4(dA0, dA1, dA2, 0.f);
    g_pnum[by*NPTS + iA] = make_float4(nA0, nA1, nA2, 0.f);
    g_pden[by*NPTS + iB] = make_float4(dB0, dB1, dB2, 0.f);
    g_pnum[by*NPTS + iB] = make_float4(nB0, nB1, nB2, 0.f);

    // ---- publish ----
    __threadfence();
    __syncthreads();
    if (tid == 0) atomicAdd(&g_ctr, 1u);

    // ---- non-finalizer blocks exit immediately (no spin, no tail work) ----
    const int flat = by * ITILES + bx;
    if (flat >= FING) return;

    // ---- finalizers wait for all partials ----
    if (tid == 0) {
        while (*((volatile unsigned*)&g_ctr) < NBLOCKS) __nanosleep(32);
    }
    __syncthreads();
    __threadfence();  // acquire

    // ---- finalize: 128 active threads = 32 i (lane) x 4 z-groups ----
    const int ii = tid & 31;           // i within this block's group of 32
    const int zg = tid >> 5;           // 0..7 (only 0..3 active)
    const int i  = flat * 32 + ii;
    float D0=0.f,D1=0.f,D2=0.f, N0=0.f,N1=0.f,N2=0.f;
    if (zg < 4) {
        const int z0 = zg * 19;
        const int z1 = min(JCHUNKS, z0 + 19);
#pragma unroll 19
        for (int z = z0; z < z1; ++z) {
            float4 pd = g_pden[z*NPTS + i];
            float4 pn = g_pnum[z*NPTS + i];
            D0 += pd.x; D1 += pd.y; D2 += pd.z;
            N0 += pn.x; N1 += pn.y; N2 += pn.z;
        }
        if (zg > 0) {
            sC[zg-1][ii][0] = D0; sC[zg-1][ii][1] = D1; sC[zg-1][ii][2] = D2;
            sC[zg-1][ii][3] = N0; sC[zg-1][ii][4] = N1; sC[zg-1][ii][5] = N2;
        }
    }
    __syncthreads();
    if (zg == 0) {
#pragma unroll
        for (int g = 0; g < 3; ++g) {
            D0 += sC[g][ii][0]; D1 += sC[g][ii][1]; D2 += sC[g][ii][2];
            N0 += sC[g][ii][3]; N1 += sC[g][ii][4]; N2 += sC[g][ii][5];
        }
        // self-pair (leave-one-out): bit-identical recompute of the loop term
        float4 xt = __ldg(reinterpret_cast<const float4*>(tx) + i);
        float4 xq = __ldg(reinterpret_cast<const float4*>(x) + i);
        float a0 = dotw(xt,W,0)*s,  a1 = dotw(xt,W,1)*s,  a2 = dotw(xt,W,2)*s;
        float t0 = dotw(xq,W,0)*s2, t1 = dotw(xq,W,1)*s2, t2 = dotw(xq,W,2)*s2;
        float k0 = ex2f(fmaf(a0, t0, -(a0*a0)));
        float k1 = ex2f(fmaf(a1, t1, -(a1*a1)));
        float k2 = ex2f(fmaf(a2, t2, -(a2*a2)));
        float y0 = __ldg(Y+3*i), y1 = __ldg(Y+3*i+1), y2 = __ldg(Y+3*i+2);
        out[3*i+0] = (N0 - k0*y0) / (D0 - k0);
        out[3*i+1] = (N1 - k1*y1) / (D1 - k1);
        out[3*i+2] = (N2 - k2*y2) / (D2 - k2);
    }

    // ---- last finalizer resets counters -> stateless across graph replays ----
    __syncthreads();
    if (tid == 0) {
        unsigned v = atomicAdd(&g_done, 1u);
        if (v == FING - 1) { g_ctr = 0; g_done = 0; __threadfence(); }
    }
}

extern "C" void kernel_launch(void* const* d_in, const int* in_sizes, int n_in,
                              void* d_out, int out_size) {
    const float* x  = (const float*)d_in[0];
    const float* tx = (const float*)d_in[1];
    const float* Y  = (const float*)d_in[2];
    const float* W  = (const float*)d_in[3];
    const float* h  = (const float*)d_in[4];
    float* out = (float*)d_out;

    fused_kernel<<<dim3(ITILES, JCHUNKS), TPB>>>(x, tx, Y, W, h, out);
}